// round 1
// baseline (speedup 1.0000x reference)
#include <cuda_runtime.h>

#define BB   4
#define CCH  64
#define HH   180
#define WWD  320
#define HWP  (HH*WWD)        // 57600
#define NPIX (BB*HWP)        // 230400
#define NELT ((size_t)NPIX*CCH)   // 14,745,600

// Scratch (static device globals: allowed; runtime allocs are not)
__device__ float g_Ql[NPIX*CCH];
__device__ float g_Qr[NPIX*CCH];
__device__ float g_Vl[NPIX*CCH];
__device__ float g_Vr[NPIX*CCH];
__device__ float g_attn[(size_t)BB*HH*WWD*WWD];   // 294.9 MB

// ---------------------------------------------------------------------------
// Kernel P: per 64-pixel tile, LayerNorm + Q projection (on LN'd x) + V
// projection (on raw x). One kernel per side (side selects output buffers).
// ---------------------------------------------------------------------------
__global__ __launch_bounds__(256) void proj_kernel(
    const float* __restrict__ x,
    const float* __restrict__ lnw, const float* __restrict__ lnb,
    const float* __restrict__ wq,  const float* __restrict__ bq,
    const float* __restrict__ wv,  const float* __restrict__ bv,
    int side)
{
    __shared__ float xs[64][68];
    __shared__ float wT[64][68];
    __shared__ float mu_s[64], rs_s[64];

    float* Qo = side ? g_Qr : g_Ql;
    float* Vo = side ? g_Vr : g_Vl;

    int tid = threadIdx.x;
    int pb  = blockIdx.x * 64;        // tile never crosses batch: HWP % 64 == 0
    int b   = pb / HWP;
    int q0  = pb - b * HWP;
    const float* xb = x + ((size_t)b * CCH) * HWP + q0;

    // load x tile [c][p] (coalesced) and wv transposed [c][o]
    #pragma unroll
    for (int i = 0; i < 16; i++) {
        int idx = i * 256 + tid;
        int c = idx >> 6, p = idx & 63;
        xs[c][p] = xb[(size_t)c * HWP + p];
        wT[idx & 63][idx >> 6] = wv[idx];
    }
    __syncthreads();

    // LayerNorm stats over channels, per pixel
    if (tid < 64) {
        float s = 0.f, ss = 0.f;
        #pragma unroll
        for (int c = 0; c < 64; c++) { float v = xs[c][tid]; s += v; ss += v*v; }
        float m = s * 0.015625f;
        mu_s[tid] = m;
        rs_s[tid] = rsqrtf(ss * 0.015625f - m*m + 1e-6f);
    }
    __syncthreads();

    int ox = tid >> 4, px = tid & 15;  // o = 4*ox+i, p = 4*px+j
    int o0 = 4 * ox;

    // ---- V = wv @ x ----
    {
        float acc[4][4];
        #pragma unroll
        for (int i = 0; i < 4; i++)
            #pragma unroll
            for (int j = 0; j < 4; j++) acc[i][j] = 0.f;
        #pragma unroll 8
        for (int c = 0; c < 64; c++) {
            float4 w4 = *(const float4*)&wT[c][4*ox];
            float4 x4 = *(const float4*)&xs[c][4*px];
            float wa[4] = {w4.x, w4.y, w4.z, w4.w};
            float xa[4] = {x4.x, x4.y, x4.z, x4.w};
            #pragma unroll
            for (int i = 0; i < 4; i++)
                #pragma unroll
                for (int j = 0; j < 4; j++) acc[i][j] += wa[i] * xa[j];
        }
        #pragma unroll
        for (int i = 0; i < 4; i++) {
            float bias = bv[o0 + i];
            float4 r = make_float4(acc[i][0]+bias, acc[i][1]+bias,
                                   acc[i][2]+bias, acc[i][3]+bias);
            *(float4*)&Vo[((size_t)(b*CCH + o0 + i)) * HWP + q0 + 4*px] = r;
        }
    }
    __syncthreads();

    // overwrite weights with wq, normalize xs in place
    #pragma unroll
    for (int i = 0; i < 16; i++) {
        int idx = i * 256 + tid;
        wT[idx & 63][idx >> 6] = wq[idx];
    }
    #pragma unroll
    for (int i = 0; i < 16; i++) {
        int idx = i * 256 + tid;
        int c = idx >> 6, p = idx & 63;
        xs[c][p] = (xs[c][p] - mu_s[p]) * rs_s[p] * lnw[c] + lnb[c];
    }
    __syncthreads();

    // ---- Q = wq @ LN(x) ----
    {
        float acc[4][4];
        #pragma unroll
        for (int i = 0; i < 4; i++)
            #pragma unroll
            for (int j = 0; j < 4; j++) acc[i][j] = 0.f;
        #pragma unroll 8
        for (int c = 0; c < 64; c++) {
            float4 w4 = *(const float4*)&wT[c][4*ox];
            float4 x4 = *(const float4*)&xs[c][4*px];
            float wa[4] = {w4.x, w4.y, w4.z, w4.w};
            float xa[4] = {x4.x, x4.y, x4.z, x4.w};
            #pragma unroll
            for (int i = 0; i < 4; i++)
                #pragma unroll
                for (int j = 0; j < 4; j++) acc[i][j] += wa[i] * xa[j];
        }
        #pragma unroll
        for (int i = 0; i < 4; i++) {
            float bias = bq[o0 + i];
            float4 r = make_float4(acc[i][0]+bias, acc[i][1]+bias,
                                   acc[i][2]+bias, acc[i][3]+bias);
            *(float4*)&Qo[((size_t)(b*CCH + o0 + i)) * HWP + q0 + 4*px] = r;
        }
    }
}

// ---------------------------------------------------------------------------
// Kernel A: attn[bh][wl][wr] = scale * sum_c Ql[c][wl] * Qr[c][wr]
// One block per (b,h). Q rows live in smem (160 KB).
// ---------------------------------------------------------------------------
__global__ __launch_bounds__(256) void attn_kernel()
{
    extern __shared__ float sm[];
    float* Qls = sm;               // [64][320]
    float* Qrs = sm + 64*320;      // [64][320]

    int tid = threadIdx.x;
    int bh = blockIdx.x;
    int b = bh / HH, h = bh - b * HH;
    const float* qlb = g_Ql + ((size_t)b * CCH) * HWP + h * WWD;
    const float* qrb = g_Qr + ((size_t)b * CCH) * HWP + h * WWD;

    #pragma unroll 4
    for (int i = 0; i < 80; i++) {
        int idx = i * 256 + tid;
        int c = idx / 320, w = idx - c * 320;
        Qls[idx] = qlb[(size_t)c * HWP + w];
        Qrs[idx] = qrb[(size_t)c * HWP + w];
    }
    __syncthreads();

    float* ap = g_attn + (size_t)bh * (WWD * WWD);
    int rx = tid >> 4, px = tid & 15;

    #pragma unroll 1
    for (int ti = 0; ti < 5; ti++) {
        #pragma unroll 1
        for (int tj = 0; tj < 5; tj++) {
            int wl = ti * 64 + 4 * rx;
            int wr = tj * 64 + 4 * px;
            float acc[4][4];
            #pragma unroll
            for (int i = 0; i < 4; i++)
                #pragma unroll
                for (int j = 0; j < 4; j++) acc[i][j] = 0.f;
            #pragma unroll 8
            for (int k = 0; k < 64; k++) {
                float4 a4 = *(const float4*)&Qls[k * 320 + wl];
                float4 b4 = *(const float4*)&Qrs[k * 320 + wr];
                float aa[4] = {a4.x, a4.y, a4.z, a4.w};
                float bb[4] = {b4.x, b4.y, b4.z, b4.w};
                #pragma unroll
                for (int i = 0; i < 4; i++)
                    #pragma unroll
                    for (int j = 0; j < 4; j++) acc[i][j] += aa[i] * bb[j];
            }
            #pragma unroll
            for (int i = 0; i < 4; i++) {
                float4 r = make_float4(acc[i][0]*0.125f, acc[i][1]*0.125f,
                                       acc[i][2]*0.125f, acc[i][3]*0.125f);
                *(float4*)&ap[(wl + i) * 320 + wr] = r;
            }
        }
    }
}

// ---------------------------------------------------------------------------
// Kernel B: row softmax over wr, F = P @ Vr^T, out_l = x_l + beta*F
// ---------------------------------------------------------------------------
__global__ __launch_bounds__(256) void r2l_kernel(
    const float* __restrict__ x_l, const float* __restrict__ beta,
    float* __restrict__ out_l)
{
    extern __shared__ float sm[];
    float* VrT  = sm;                        // [320][68] : [v][c]
    float* Pt   = sm + 320*68;               // [64][68]  : [v_local][wl_local]
    float* rmax = sm + 320*68 + 64*68;       // [320]
    float* rinv = rmax + 320;

    int tid = threadIdx.x;
    int bh = blockIdx.x;
    int b = bh / HH, h = bh - b * HH;
    const float* vrb = g_Vr + ((size_t)b * CCH) * HWP + h * WWD;

    #pragma unroll 4
    for (int i = 0; i < 80; i++) {
        int idx = i * 256 + tid;
        int c = idx / 320, v = idx - c * 320;
        VrT[v * 68 + c] = vrb[(size_t)c * HWP + v];
    }

    const float* ap = g_attn + (size_t)bh * (WWD * WWD);
    int wid = tid >> 5, lane = tid & 31;
    for (int row = wid; row < 320; row += 8) {
        const float* rp = ap + row * 320;
        float a[10], m = -1e30f;
        #pragma unroll
        for (int j = 0; j < 10; j++) { a[j] = rp[lane + 32*j]; m = fmaxf(m, a[j]); }
        #pragma unroll
        for (int o = 16; o > 0; o >>= 1) m = fmaxf(m, __shfl_xor_sync(0xffffffffu, m, o));
        float s = 0.f;
        #pragma unroll
        for (int j = 0; j < 10; j++) s += __expf(a[j] - m);
        #pragma unroll
        for (int o = 16; o > 0; o >>= 1) s += __shfl_xor_sync(0xffffffffu, s, o);
        if (lane == 0) { rmax[row] = m; rinv[row] = 1.0f / s; }
    }
    __syncthreads();

    int cx = tid >> 4, px = tid & 15;   // c = 4cx+i, wl_local = 4px+j
    const float* xb = x_l + ((size_t)b * CCH) * HWP + h * WWD;
    float* ob = out_l + ((size_t)b * CCH) * HWP + h * WWD;

    #pragma unroll 1
    for (int wt = 0; wt < 5; wt++) {
        int wl0 = wt * 64;
        float acc[4][4];
        #pragma unroll
        for (int i = 0; i < 4; i++)
            #pragma unroll
            for (int j = 0; j < 4; j++) acc[i][j] = 0.f;

        #pragma unroll 1
        for (int vt = 0; vt < 5; vt++) {
            __syncthreads();
            #pragma unroll
            for (int i = 0; i < 16; i++) {
                int idx = i * 256 + tid;
                int r = idx >> 6, vc = idx & 63;
                float av = ap[(wl0 + r) * 320 + vt * 64 + vc];
                Pt[vc * 68 + r] = __expf(av - rmax[wl0 + r]) * rinv[wl0 + r];
            }
            __syncthreads();
            #pragma unroll 8
            for (int v = 0; v < 64; v++) {
                float4 p4 = *(const float4*)&Pt[v * 68 + 4 * px];
                float4 v4 = *(const float4*)&VrT[(vt * 64 + v) * 68 + 4 * cx];
                float pa[4] = {p4.x, p4.y, p4.z, p4.w};
                float va[4] = {v4.x, v4.y, v4.z, v4.w};
                #pragma unroll
                for (int i = 0; i < 4; i++)
                    #pragma unroll
                    for (int j = 0; j < 4; j++) acc[i][j] += va[i] * pa[j];
            }
        }
        #pragma unroll
        for (int i = 0; i < 4; i++) {
            int c = 4 * cx + i;
            float bt = beta[c];
            float4 xv = *(const float4*)&xb[(size_t)c * HWP + wl0 + 4 * px];
            float4 r = make_float4(xv.x + bt*acc[i][0], xv.y + bt*acc[i][1],
                                   xv.z + bt*acc[i][2], xv.w + bt*acc[i][3]);
            *(float4*)&ob[(size_t)c * HWP + wl0 + 4 * px] = r;
        }
    }
}

// ---------------------------------------------------------------------------
// Kernel C: column softmax over wl, F = P2^T-weighted Vl, out_r = x_r + gamma*F
// ---------------------------------------------------------------------------
__global__ __launch_bounds__(256) void l2r_kernel(
    const float* __restrict__ x_r, const float* __restrict__ gamma,
    float* __restrict__ out_r)
{
    extern __shared__ float sm[];
    float* VlT  = sm;                        // [320][68] : [wl][c]
    float* Ps   = sm + 320*68;               // [64][68]  : [wl_local][wr_local]
    float* cmax = sm + 320*68 + 64*68;       // [320]
    float* cinv = cmax + 320;

    int tid = threadIdx.x;
    int bh = blockIdx.x;
    int b = bh / HH, h = bh - b * HH;
    const float* vlb = g_Vl + ((size_t)b * CCH) * HWP + h * WWD;

    #pragma unroll 4
    for (int i = 0; i < 80; i++) {
        int idx = i * 256 + tid;
        int c = idx / 320, w = idx - c * 320;
        VlT[w * 68 + c] = vlb[(size_t)c * HWP + w];
    }

    const float* ap = g_attn + (size_t)bh * (WWD * WWD);
    // column stats: thread tid owns column tid (all) and 256+tid (tid<64)
    {
        float m1 = -1e30f, m2 = -1e30f;
        for (int row = 0; row < 320; row++) {
            const float* rp = ap + row * 320;
            m1 = fmaxf(m1, rp[tid]);
            if (tid < 64) m2 = fmaxf(m2, rp[256 + tid]);
        }
        float s1 = 0.f, s2 = 0.f;
        for (int row = 0; row < 320; row++) {
            const float* rp = ap + row * 320;
            s1 += __expf(rp[tid] - m1);
            if (tid < 64) s2 += __expf(rp[256 + tid] - m2);
        }
        cmax[tid] = m1; cinv[tid] = 1.0f / s1;
        if (tid < 64) { cmax[256 + tid] = m2; cinv[256 + tid] = 1.0f / s2; }
    }
    __syncthreads();

    int cx = tid >> 4, px = tid & 15;   // c = 4cx+i, wr_local = 4px+j
    const float* xb = x_r + ((size_t)b * CCH) * HWP + h * WWD;
    float* ob = out_r + ((size_t)b * CCH) * HWP + h * WWD;

    #pragma unroll 1
    for (int wrt = 0; wrt < 5; wrt++) {
        int wr0 = wrt * 64;
        float acc[4][4];
        #pragma unroll
        for (int i = 0; i < 4; i++)
            #pragma unroll
            for (int j = 0; j < 4; j++) acc[i][j] = 0.f;

        #pragma unroll 1
        for (int wlt = 0; wlt < 5; wlt++) {
            __syncthreads();
            #pragma unroll
            for (int i = 0; i < 16; i++) {
                int idx = i * 256 + tid;
                int r = idx >> 6, vc = idx & 63;
                float av = ap[(wlt * 64 + r) * 320 + wr0 + vc];
                Ps[r * 68 + vc] = __expf(av - cmax[wr0 + vc]) * cinv[wr0 + vc];
            }
            __syncthreads();
            #pragma unroll 8
            for (int k = 0; k < 64; k++) {
                float4 p4 = *(const float4*)&Ps[k * 68 + 4 * px];
                float4 v4 = *(const float4*)&VlT[(wlt * 64 + k) * 68 + 4 * cx];
                float pa[4] = {p4.x, p4.y, p4.z, p4.w};
                float va[4] = {v4.x, v4.y, v4.z, v4.w};
                #pragma unroll
                for (int i = 0; i < 4; i++)
                    #pragma unroll
                    for (int j = 0; j < 4; j++) acc[i][j] += va[i] * pa[j];
            }
        }
        #pragma unroll
        for (int i = 0; i < 4; i++) {
            int c = 4 * cx + i;
            float gm = gamma[c];
            float4 xv = *(const float4*)&xb[(size_t)c * HWP + wr0 + 4 * px];
            float4 r = make_float4(xv.x + gm*acc[i][0], xv.y + gm*acc[i][1],
                                   xv.z + gm*acc[i][2], xv.w + gm*acc[i][3]);
            *(float4*)&ob[(size_t)c * HWP + wr0 + 4 * px] = r;
        }
    }
}

// ---------------------------------------------------------------------------
extern "C" void kernel_launch(void* const* d_in, const int* in_sizes, int n_in,
                              void* d_out, int out_size)
{
    const float* x_l    = (const float*)d_in[0];
    const float* x_r    = (const float*)d_in[1];
    const float* ln_l_w = (const float*)d_in[2];
    const float* ln_l_b = (const float*)d_in[3];
    const float* ln_r_w = (const float*)d_in[4];
    const float* ln_r_b = (const float*)d_in[5];
    const float* wq_l   = (const float*)d_in[6];
    const float* bq_l   = (const float*)d_in[7];
    const float* wq_r   = (const float*)d_in[8];
    const float* bq_r   = (const float*)d_in[9];
    const float* wv_l   = (const float*)d_in[10];
    const float* bv_l   = (const float*)d_in[11];
    const float* wv_r   = (const float*)d_in[12];
    const float* bv_r   = (const float*)d_in[13];
    const float* beta   = (const float*)d_in[14];
    const float* gamma  = (const float*)d_in[15];

    float* out_l = (float*)d_out;
    float* out_r = out_l + NELT;

    cudaFuncSetAttribute(attn_kernel, cudaFuncAttributeMaxDynamicSharedMemorySize, 163840);
    cudaFuncSetAttribute(r2l_kernel,  cudaFuncAttributeMaxDynamicSharedMemorySize, 107008);
    cudaFuncSetAttribute(l2r_kernel,  cudaFuncAttributeMaxDynamicSharedMemorySize, 107008);

    proj_kernel<<<NPIX/64, 256>>>(x_l, ln_l_w, ln_l_b, wq_l, bq_l, wv_l, bv_l, 0);
    proj_kernel<<<NPIX/64, 256>>>(x_r, ln_r_w, ln_r_b, wq_r, bq_r, wv_r, bv_r, 1);
    attn_kernel<<<BB*HH, 256, 163840>>>();
    r2l_kernel<<<BB*HH, 256, 107008>>>(x_l, beta, out_l);
    l2r_kernel<<<BB*HH, 256, 107008>>>(x_r, gamma, out_r);
}